// round 4
// baseline (speedup 1.0000x reference)
#include <cuda_runtime.h>
#include <math.h>
#include <stdint.h>

// Problem constants
#define kE   2048
#define kHQ  32
#define kHKV 8
#define kHD  64
#define kB   2
#define kT   2048
#define kM   (kB * kT)          // 4096 rows (B*T)
#define kKVN (2 * kHKV * kHD)   // 1024

// Scratch (device globals — allocation-free per harness rules)
__device__ float g_q[kM * kE];      // q projection  (B*T, E)
__device__ float g_kv[kM * kKVN];   // kv projection (B*T, 1024): k [0,512), v [512,1024)
__device__ float g_ao[kM * kE];     // attention output (B*T, E)

// ---------------------------------------------------------------------------
// tf32 helpers (legacy mma.sync path)
// ---------------------------------------------------------------------------
__device__ __forceinline__ uint32_t f2tf32(float v) {
    uint32_t r;
    asm("cvt.rna.tf32.f32 %0, %1;" : "=r"(r) : "f"(v));
    return r;
}

__device__ __forceinline__ void split3(float v, uint32_t& hi, uint32_t& lo) {
    uint32_t h = f2tf32(v);
    float hf = __uint_as_float(h);   // tf32 bits are a valid fp32
    lo = f2tf32(v - hf);
    hi = h;
}

__device__ __forceinline__ void mma_tf32(float* d, const uint32_t* a, const uint32_t* b) {
    asm volatile(
        "mma.sync.aligned.m16n8k8.row.col.f32.tf32.tf32.f32 "
        "{%0,%1,%2,%3},{%4,%5,%6,%7},{%8,%9},{%0,%1,%2,%3};\n"
        : "+f"(d[0]), "+f"(d[1]), "+f"(d[2]), "+f"(d[3])
        : "r"(a[0]), "r"(a[1]), "r"(a[2]), "r"(a[3]), "r"(b[0]), "r"(b[1]));
}

// ---------------------------------------------------------------------------
// GEMM: C[M,N] = A[M,K] * W[N,K]^T   (torch Linear), tf32x3 (~fp32 accurate)
// CTA tile 128x128, K-tile 32, 8 warps (warp tile 32x64).
// Smem holds PRE-SPLIT tf32 (hi,lo) interleaved pairs, double-buffered.
// Row stride 72 words (== 8 mod 32): conflict-free LDS.64 fragment loads.
// ---------------------------------------------------------------------------
#define GSTR      72                 // words per row (36 elems * 2)
#define GTILE_W   (128 * GSTR)       // words per (matrix, stage)
#define GEMM_SMEM (4 * GTILE_W * 4)  // 2 matrices * 2 stages * 4B

__global__ __launch_bounds__(256) void gemm_xwT(
        const float* __restrict__ A, const float* __restrict__ W,
        float* __restrict__ C, int N, int K) {
    extern __shared__ uint32_t smg[];
    // [As stage0][As stage1][Ws stage0][Ws stage1]
    const int tid  = threadIdx.x;
    const int lane = tid & 31;
    const int wid  = tid >> 5;
    const int wm   = wid >> 1;      // 0..3 (32 rows each)
    const int wn   = wid & 1;       // 0..1 (64 cols each)
    const int m0   = blockIdx.y * 128;
    const int n0   = blockIdx.x * 128;

    const int ldrow = tid >> 3;          // 0..31
    const int ldcol = (tid & 7) << 2;    // 0,4,..,28

    float acc[2][8][4];
#pragma unroll
    for (int i = 0; i < 2; i++)
#pragma unroll
        for (int j = 0; j < 8; j++)
#pragma unroll
            for (int k = 0; k < 4; k++) acc[i][j][k] = 0.f;

    float4 ra[4], rw[4];

    // ---- prologue: load + split/store tile 0 ----
#pragma unroll
    for (int p = 0; p < 4; p++) {
        int row = p * 32 + ldrow;
        ra[p] = *(const float4*)&A[(size_t)(m0 + row) * K + ldcol];
        rw[p] = *(const float4*)&W[(size_t)(n0 + row) * K + ldcol];
    }
    {
        uint32_t* As = smg;
        uint32_t* Ws = smg + 2 * GTILE_W;
#pragma unroll
        for (int p = 0; p < 4; p++) {
            int row = p * 32 + ldrow;
            uint32_t h0,l0,h1,l1,h2,l2,h3,l3;
            split3(ra[p].x,h0,l0); split3(ra[p].y,h1,l1);
            split3(ra[p].z,h2,l2); split3(ra[p].w,h3,l3);
            uint32_t* d = As + row * GSTR + ldcol * 2;
            *(uint4*)d       = make_uint4(h0,l0,h1,l1);
            *(uint4*)(d + 4) = make_uint4(h2,l2,h3,l3);
            split3(rw[p].x,h0,l0); split3(rw[p].y,h1,l1);
            split3(rw[p].z,h2,l2); split3(rw[p].w,h3,l3);
            d = Ws + row * GSTR + ldcol * 2;
            *(uint4*)d       = make_uint4(h0,l0,h1,l1);
            *(uint4*)(d + 4) = make_uint4(h2,l2,h3,l3);
        }
    }
    __syncthreads();

    const int nkt = K >> 5;
    const int arow0 = wm * 32 + (lane >> 2);   // mt adds +16
    const int brow0 = wn * 64 + (lane >> 2);   // nt adds *8
    const int fcol  = lane & 3;

    for (int kt = 0; kt < nkt; kt++) {
        const int cur = kt & 1;
        // prefetch next tile into registers (latency hidden by compute)
        if (kt + 1 < nkt) {
            const int koff = (kt + 1) << 5;
#pragma unroll
            for (int p = 0; p < 4; p++) {
                int row = p * 32 + ldrow;
                ra[p] = *(const float4*)&A[(size_t)(m0 + row) * K + koff + ldcol];
                rw[p] = *(const float4*)&W[(size_t)(n0 + row) * K + koff + ldcol];
            }
        }

        const uint32_t* As = smg + cur * GTILE_W;
        const uint32_t* Ws = smg + 2 * GTILE_W + cur * GTILE_W;

#pragma unroll
        for (int k8 = 0; k8 < 4; k8++) {
            const int kk = k8 * 8 + fcol;
            // a fragments (hi,lo interleaved -> one LDS.64 per element)
            uint32_t ahi[2][4], alo[2][4];
#pragma unroll
            for (int mt = 0; mt < 2; mt++) {
                const int r = arow0 + mt * 16;
                uint2 e0 = *(const uint2*)&As[r * GSTR + kk * 2];
                uint2 e1 = *(const uint2*)&As[(r + 8) * GSTR + kk * 2];
                uint2 e2 = *(const uint2*)&As[r * GSTR + (kk + 4) * 2];
                uint2 e3 = *(const uint2*)&As[(r + 8) * GSTR + (kk + 4) * 2];
                ahi[mt][0]=e0.x; alo[mt][0]=e0.y;
                ahi[mt][1]=e1.x; alo[mt][1]=e1.y;
                ahi[mt][2]=e2.x; alo[mt][2]=e2.y;
                ahi[mt][3]=e3.x; alo[mt][3]=e3.y;
            }
#pragma unroll
            for (int nt = 0; nt < 8; nt++) {
                const int r = brow0 + nt * 8;
                uint2 b0 = *(const uint2*)&Ws[r * GSTR + kk * 2];
                uint2 b1 = *(const uint2*)&Ws[r * GSTR + (kk + 4) * 2];
                uint32_t bhi[2] = {b0.x, b1.x};
                uint32_t blo[2] = {b0.y, b1.y};
                // tf32x3: lo*hi + hi*lo + hi*hi (interleave mt for ILP)
                mma_tf32(acc[0][nt], alo[0], bhi);
                mma_tf32(acc[1][nt], alo[1], bhi);
                mma_tf32(acc[0][nt], ahi[0], blo);
                mma_tf32(acc[1][nt], ahi[1], blo);
                mma_tf32(acc[0][nt], ahi[0], bhi);
                mma_tf32(acc[1][nt], ahi[1], bhi);
            }
        }

        // split + store prefetched tile into the other stage
        if (kt + 1 < nkt) {
            uint32_t* Asn = smg + (cur ^ 1) * GTILE_W;
            uint32_t* Wsn = smg + 2 * GTILE_W + (cur ^ 1) * GTILE_W;
#pragma unroll
            for (int p = 0; p < 4; p++) {
                int row = p * 32 + ldrow;
                uint32_t h0,l0,h1,l1,h2,l2,h3,l3;
                split3(ra[p].x,h0,l0); split3(ra[p].y,h1,l1);
                split3(ra[p].z,h2,l2); split3(ra[p].w,h3,l3);
                uint32_t* d = Asn + row * GSTR + ldcol * 2;
                *(uint4*)d       = make_uint4(h0,l0,h1,l1);
                *(uint4*)(d + 4) = make_uint4(h2,l2,h3,l3);
                split3(rw[p].x,h0,l0); split3(rw[p].y,h1,l1);
                split3(rw[p].z,h2,l2); split3(rw[p].w,h3,l3);
                d = Wsn + row * GSTR + ldcol * 2;
                *(uint4*)d       = make_uint4(h0,l0,h1,l1);
                *(uint4*)(d + 4) = make_uint4(h2,l2,h3,l3);
            }
        }
        __syncthreads();
    }

#pragma unroll
    for (int mt = 0; mt < 2; mt++) {
        int r = m0 + wm * 32 + mt * 16 + (lane >> 2);
#pragma unroll
        for (int nt = 0; nt < 8; nt++) {
            int c = n0 + wn * 64 + nt * 8 + ((lane & 3) << 1);
            C[(size_t)r * N + c]           = acc[mt][nt][0];
            C[(size_t)r * N + c + 1]       = acc[mt][nt][1];
            C[(size_t)(r + 8) * N + c]     = acc[mt][nt][2];
            C[(size_t)(r + 8) * N + c + 1] = acc[mt][nt][3];
        }
    }
}

// ---------------------------------------------------------------------------
// Flash attention (causal, GQA): per-CTA 64 query rows of one (b, hq) head.
// 4 warps x 16 rows; online softmax; tf32 mma for QK^T and P*V.
// Smem tiles hold PRE-CONVERTED tf32 words (cvt hoisted out of inner loops).
// ---------------------------------------------------------------------------
#define QSTRIDE 68   // == 4 (mod 32)  (Q, K, P buffers)
#define VSTRIDE 72   // == 8 (mod 32)  (V buffer)
#define ATTN_SMEM ((64 * QSTRIDE * 3 + 64 * VSTRIDE) * 4)

__global__ __launch_bounds__(128) void attn_kernel(
        const float* __restrict__ q, const float* __restrict__ kv,
        float* __restrict__ o_out) {
    extern __shared__ uint32_t sm[];
    uint32_t* Qs = sm;
    uint32_t* Ks = Qs + 64 * QSTRIDE;
    uint32_t* Ps = Ks + 64 * QSTRIDE;
    uint32_t* Vs = Ps + 64 * QSTRIDE;

    const int tid  = threadIdx.x;
    const int lane = tid & 31;
    const int w    = tid >> 5;
    const int qb   = blockIdx.x;     // query block (64 rows)
    const int bh   = blockIdx.y;     // b * 32 + hq
    const int b    = bh >> 5;
    const int hq   = bh & 31;
    const int hkv  = hq >> 2;        // G = 4

    const int ldrow = tid >> 4;          // 0..7
    const int ldcol = (tid & 15) << 2;   // 0..60

    // Load Q tile, pre-scaled by 1/sqrt(HD), converted to tf32 once
#pragma unroll
    for (int p = 0; p < 8; p++) {
        int row = p * 8 + ldrow;
        const float4 v = *(const float4*)&q[((size_t)(b * kT + qb * 64 + row)) * kE + hq * kHD + ldcol];
        uint4 sv = make_uint4(f2tf32(v.x * 0.125f), f2tf32(v.y * 0.125f),
                              f2tf32(v.z * 0.125f), f2tf32(v.w * 0.125f));
        *(uint4*)&Qs[row * QSTRIDE + ldcol] = sv;
    }

    float mrow0 = -INFINITY, mrow1 = -INFINITY;
    float lrow0 = 0.f, lrow1 = 0.f;
    float o[8][4];
#pragma unroll
    for (int nt = 0; nt < 8; nt++)
#pragma unroll
        for (int i = 0; i < 4; i++) o[nt][i] = 0.f;

    const int rloc = w * 16 + (lane >> 2);   // thread's row (and rloc+8)

    for (int j = 0; j <= qb; j++) {
        // Load K, V tiles (64x64 each), convert to tf32 at store
#pragma unroll
        for (int p = 0; p < 8; p++) {
            int row = p * 8 + ldrow;
            size_t base = ((size_t)(b * kT + j * 64 + row)) * kKVN + hkv * kHD + ldcol;
            float4 kvr = *(const float4*)&kv[base];
            float4 vvr = *(const float4*)&kv[base + 512];
            *(uint4*)&Ks[row * QSTRIDE + ldcol] =
                make_uint4(f2tf32(kvr.x), f2tf32(kvr.y), f2tf32(kvr.z), f2tf32(kvr.w));
            *(uint4*)&Vs[row * VSTRIDE + ldcol] =
                make_uint4(f2tf32(vvr.x), f2tf32(vvr.y), f2tf32(vvr.z), f2tf32(vvr.w));
        }
        __syncthreads();

        // S = Q * K^T  (this warp's 16 rows x 64 cols)
        float s[8][4];
#pragma unroll
        for (int nt = 0; nt < 8; nt++) { s[nt][0] = s[nt][1] = s[nt][2] = s[nt][3] = 0.f; }

#pragma unroll
        for (int k8 = 0; k8 < 8; k8++) {
            const int kk = k8 * 8 + (lane & 3);
            uint32_t a[4];
            a[0] = Qs[rloc * QSTRIDE + kk];
            a[1] = Qs[(rloc + 8) * QSTRIDE + kk];
            a[2] = Qs[rloc * QSTRIDE + kk + 4];
            a[3] = Qs[(rloc + 8) * QSTRIDE + kk + 4];
#pragma unroll
            for (int nt = 0; nt < 8; nt++) {
                const int kr = nt * 8 + (lane >> 2);
                uint32_t bb[2];
                bb[0] = Ks[kr * QSTRIDE + kk];
                bb[1] = Ks[kr * QSTRIDE + kk + 4];
                mma_tf32(s[nt], a, bb);
            }
        }

        // Causal mask on the diagonal block
        if (j == qb) {
#pragma unroll
            for (int nt = 0; nt < 8; nt++) {
                int c0 = nt * 8 + ((lane & 3) << 1);
                if (c0     > rloc)     s[nt][0] = -INFINITY;
                if (c0 + 1 > rloc)     s[nt][1] = -INFINITY;
                if (c0     > rloc + 8) s[nt][2] = -INFINITY;
                if (c0 + 1 > rloc + 8) s[nt][3] = -INFINITY;
            }
        }

        // Online softmax
        float mx0 = -INFINITY, mx1 = -INFINITY;
#pragma unroll
        for (int nt = 0; nt < 8; nt++) {
            mx0 = fmaxf(mx0, fmaxf(s[nt][0], s[nt][1]));
            mx1 = fmaxf(mx1, fmaxf(s[nt][2], s[nt][3]));
        }
        mx0 = fmaxf(mx0, __shfl_xor_sync(0xffffffffu, mx0, 1));
        mx0 = fmaxf(mx0, __shfl_xor_sync(0xffffffffu, mx0, 2));
        mx1 = fmaxf(mx1, __shfl_xor_sync(0xffffffffu, mx1, 1));
        mx1 = fmaxf(mx1, __shfl_xor_sync(0xffffffffu, mx1, 2));

        float mnew0 = fmaxf(mrow0, mx0);
        float mnew1 = fmaxf(mrow1, mx1);
        float alpha0 = __expf(mrow0 - mnew0);
        float alpha1 = __expf(mrow1 - mnew1);
        mrow0 = mnew0; mrow1 = mnew1;

        float sum0 = 0.f, sum1 = 0.f;
#pragma unroll
        for (int nt = 0; nt < 8; nt++) {
            s[nt][0] = __expf(s[nt][0] - mnew0); sum0 += s[nt][0];
            s[nt][1] = __expf(s[nt][1] - mnew0); sum0 += s[nt][1];
            s[nt][2] = __expf(s[nt][2] - mnew1); sum1 += s[nt][2];
            s[nt][3] = __expf(s[nt][3] - mnew1); sum1 += s[nt][3];
        }
        sum0 += __shfl_xor_sync(0xffffffffu, sum0, 1);
        sum0 += __shfl_xor_sync(0xffffffffu, sum0, 2);
        sum1 += __shfl_xor_sync(0xffffffffu, sum1, 1);
        sum1 += __shfl_xor_sync(0xffffffffu, sum1, 2);

        lrow0 = lrow0 * alpha0 + sum0;
        lrow1 = lrow1 * alpha1 + sum1;

#pragma unroll
        for (int nt = 0; nt < 8; nt++) {
            o[nt][0] *= alpha0; o[nt][1] *= alpha0;
            o[nt][2] *= alpha1; o[nt][3] *= alpha1;
        }

        // C-frag -> A-frag via smem, converted to tf32 at store
#pragma unroll
        for (int nt = 0; nt < 8; nt++) {
            int pc = nt * 8 + ((lane & 3) << 1);
            Ps[rloc * QSTRIDE + pc]           = f2tf32(s[nt][0]);
            Ps[rloc * QSTRIDE + pc + 1]       = f2tf32(s[nt][1]);
            Ps[(rloc + 8) * QSTRIDE + pc]     = f2tf32(s[nt][2]);
            Ps[(rloc + 8) * QSTRIDE + pc + 1] = f2tf32(s[nt][3]);
        }
        __syncwarp();

        // O += P * V
#pragma unroll
        for (int k8 = 0; k8 < 8; k8++) {
            const int kk = k8 * 8 + (lane & 3);
            uint32_t a[4];
            a[0] = Ps[rloc * QSTRIDE + kk];
            a[1] = Ps[(rloc + 8) * QSTRIDE + kk];
            a[2] = Ps[rloc * QSTRIDE + kk + 4];
            a[3] = Ps[(rloc + 8) * QSTRIDE + kk + 4];
#pragma unroll
            for (int nt = 0; nt < 8; nt++) {
                uint32_t bb[2];
                bb[0] = Vs[kk * VSTRIDE + nt * 8 + (lane >> 2)];
                bb[1] = Vs[(kk + 4) * VSTRIDE + nt * 8 + (lane >> 2)];
                mma_tf32(o[nt], a, bb);
            }
        }
        __syncthreads();   // protect Ks/Vs before next block load
    }

    // Normalize and write out
    float inv0 = 1.f / lrow0;
    float inv1 = 1.f / lrow1;
    size_t r0 = (size_t)(b * kT + qb * 64 + rloc) * kE + hq * kHD;
    size_t r1 = (size_t)(b * kT + qb * 64 + rloc + 8) * kE + hq * kHD;
#pragma unroll
    for (int nt = 0; nt < 8; nt++) {
        int c = nt * 8 + ((lane & 3) << 1);
        o_out[r0 + c]     = o[nt][0] * inv0;
        o_out[r0 + c + 1] = o[nt][1] * inv0;
        o_out[r1 + c]     = o[nt][2] * inv1;
        o_out[r1 + c + 1] = o[nt][3] * inv1;
    }
}

// ---------------------------------------------------------------------------
// Launch
// ---------------------------------------------------------------------------
extern "C" void kernel_launch(void* const* d_in, const int* in_sizes, int n_in,
                              void* d_out, int out_size) {
    (void)in_sizes; (void)n_in; (void)out_size;
    const float* x   = (const float*)d_in[0];
    const float* Wq  = (const float*)d_in[1];
    const float* Wkv = (const float*)d_in[2];
    const float* Wo  = (const float*)d_in[3];
    float* out = (float*)d_out;

    float *q, *kvb, *ao;
    cudaGetSymbolAddress((void**)&q,   g_q);
    cudaGetSymbolAddress((void**)&kvb, g_kv);
    cudaGetSymbolAddress((void**)&ao,  g_ao);

    cudaFuncSetAttribute(gemm_xwT,
                         cudaFuncAttributeMaxDynamicSharedMemorySize, GEMM_SMEM);
    cudaFuncSetAttribute(attn_kernel,
                         cudaFuncAttributeMaxDynamicSharedMemorySize, ATTN_SMEM);

    dim3 blk(256);
    gemm_xwT<<<dim3(kE / 128,   kM / 128), blk, GEMM_SMEM>>>(x,  Wq,  q,   kE,   kE);
    gemm_xwT<<<dim3(kKVN / 128, kM / 128), blk, GEMM_SMEM>>>(x,  Wkv, kvb, kKVN, kE);
    attn_kernel<<<dim3(kT / 64, kB * kHQ), dim3(128), ATTN_SMEM>>>(q, kvb, ao);
    gemm_xwT<<<dim3(kE / 128,   kM / 128), blk, GEMM_SMEM>>>(ao, Wo,  out, kE,   kE);
}

// round 6
// speedup vs baseline: 1.8703x; 1.8703x over previous
#include <cuda_runtime.h>
#include <cuda_bf16.h>
#include <math.h>
#include <stdint.h>

// Problem constants
#define kE   2048
#define kHQ  32
#define kHKV 8
#define kHD  64
#define kB   2
#define kT   2048
#define kM   (kB * kT)          // 4096 rows (B*T)
#define kKVN (2 * kHKV * kHD)   // 1024

// ---------------------------------------------------------------------------
// Device-global scratch (allocation-free per harness rules)
// ---------------------------------------------------------------------------
__device__ float g_q[kM * kE];       // q projection  (fp32)
__device__ float g_kv[kM * kKVN];    // kv projection (fp32): k [0,512), v [512,1024)
__device__ __nv_bfloat16 g_xhi[kM * kE],     g_xlo[kM * kE];
__device__ __nv_bfloat16 g_wqhi[kE * kE],    g_wqlo[kE * kE];
__device__ __nv_bfloat16 g_wkvhi[kKVN * kE], g_wkvlo[kKVN * kE];
__device__ __nv_bfloat16 g_wohi[kE * kE],    g_wolo[kE * kE];
__device__ __nv_bfloat16 g_aohi[kM * kE],    g_aolo[kM * kE];

// ---------------------------------------------------------------------------
// Helpers
// ---------------------------------------------------------------------------
__device__ __forceinline__ uint32_t smem_u32(const void* p) {
    uint32_t a;
    asm("{ .reg .u64 t; cvta.to.shared.u64 t, %1; cvt.u32.u64 %0, t; }"
        : "=r"(a) : "l"(p));
    return a;
}

__device__ __forceinline__ void cp16(uint32_t saddr, const void* g) {
    asm volatile("cp.async.cg.shared.global [%0], [%1], 16;"
                 :: "r"(saddr), "l"(g) : "memory");
}
#define CP_COMMIT()  asm volatile("cp.async.commit_group;" ::: "memory")
#define CP_WAIT(n)   asm volatile("cp.async.wait_group %0;" :: "n"(n) : "memory")

// Legacy bf16 tensor op: D(16x8,f32) += A(16x16,bf16) * B(16x8,bf16)
__device__ __forceinline__ void mma_bf16(float* d, const uint32_t* a, const uint32_t* b) {
    asm volatile(
        "mma.sync.aligned.m16n8k16.row.col.f32.bf16.bf16.f32 "
        "{%0,%1,%2,%3},{%4,%5,%6,%7},{%8,%9},{%0,%1,%2,%3};\n"
        : "+f"(d[0]), "+f"(d[1]), "+f"(d[2]), "+f"(d[3])
        : "r"(a[0]), "r"(a[1]), "r"(a[2]), "r"(a[3]), "r"(b[0]), "r"(b[1]));
}

// bf16 split: v = hi + lo + O(2^-18 v)
__device__ __forceinline__ void splitbf(float v, __nv_bfloat16& h, __nv_bfloat16& l) {
    h = __float2bfloat16(v);
    l = __float2bfloat16(v - __bfloat162float(h));
}

__global__ __launch_bounds__(256) void split_kernel(
        const float* __restrict__ in, __nv_bfloat16* __restrict__ hi,
        __nv_bfloat16* __restrict__ lo, int n4) {
    int i = blockIdx.x * blockDim.x + threadIdx.x;
    if (i >= n4) return;
    float4 v = ((const float4*)in)[i];
    __nv_bfloat16 h0, h1, h2, h3, l0, l1, l2, l3;
    splitbf(v.x, h0, l0); splitbf(v.y, h1, l1);
    splitbf(v.z, h2, l2); splitbf(v.w, h3, l3);
    __nv_bfloat162* hp = (__nv_bfloat162*)hi;
    __nv_bfloat162* lp = (__nv_bfloat162*)lo;
    hp[2*i]   = __nv_bfloat162(h0, h1);
    hp[2*i+1] = __nv_bfloat162(h2, h3);
    lp[2*i]   = __nv_bfloat162(l0, l1);
    lp[2*i+1] = __nv_bfloat162(l2, l3);
}

// ---------------------------------------------------------------------------
// GEMM: C[M,N] = A[M,K] * W[N,K]^T, bf16x3 on legacy mma.m16n8k16.
// CTA tile 128x128, K-tile 32, 8 warps (warp tile 32x64).
// Inputs pre-split into bf16 hi/lo planes. cp.async double-buffered staging.
// Smem planes: 128 rows x 16 u32-words (2 bf16/word), padded to stride 20
// words (rows*20 mod 32 all distinct) -> conflict-free fragment LDS.
// ---------------------------------------------------------------------------
#define SPLANE_W 2560                       // 128 * 20 u32 words
#define SPLANE_B (SPLANE_W * 4)             // 10240 bytes
#define STAGE_B  (4 * SPLANE_B)             // Ahi, Alo, Whi, Wlo
#define GEMM_SMEM (2 * STAGE_B)             // 81920 bytes

__global__ __launch_bounds__(256) void gemm_bf3(
        const __nv_bfloat16* __restrict__ Ahi, const __nv_bfloat16* __restrict__ Alo,
        const __nv_bfloat16* __restrict__ Whi, const __nv_bfloat16* __restrict__ Wlo,
        float* __restrict__ C, int N, int K) {
    extern __shared__ char smem[];
    const uint32_t sbase = smem_u32(smem);

    const int tid  = threadIdx.x;
    const int lane = tid & 31;
    const int wid  = tid >> 5;
    const int wm   = wid >> 1;        // 0..3
    const int wn   = wid & 1;         // 0..1
    const int m0   = blockIdx.y * 128;
    const int n0   = blockIdx.x * 128;

    float acc[2][8][4];
#pragma unroll
    for (int i = 0; i < 2; i++)
#pragma unroll
        for (int j = 0; j < 8; j++)
#pragma unroll
            for (int k = 0; k < 4; k++) acc[i][j][k] = 0.f;

    const size_t gs = (size_t)K * 2;  // bytes per global row
    const int crow  = tid >> 1;       // 0..127
    const int cbo   = (tid & 1) << 5; // 0 or 32 bytes within the 64B row

    const char* pA[2] = {(const char*)Ahi, (const char*)Alo};
    const char* pW[2] = {(const char*)Whi, (const char*)Wlo};

    const int NKT = K >> 5;

    // async copy of one 32-k tile into stage s
    auto copy_tile = [&](int s, int kt) {
        const uint32_t st = sbase + s * STAGE_B + crow * 80 + cbo;
        const size_t goA = (size_t)(m0 + crow) * gs + (size_t)kt * 64 + cbo;
        const size_t goW = (size_t)(n0 + crow) * gs + (size_t)kt * 64 + cbo;
#pragma unroll
        for (int pl = 0; pl < 2; pl++) {
            cp16(st + pl * SPLANE_B,             pA[pl] + goA);
            cp16(st + pl * SPLANE_B + 16,        pA[pl] + goA + 16);
            cp16(st + (2 + pl) * SPLANE_B,       pW[pl] + goW);
            cp16(st + (2 + pl) * SPLANE_B + 16,  pW[pl] + goW + 16);
        }
    };

    copy_tile(0, 0);
    CP_COMMIT();

    const int rq = lane >> 2;       // 0..7
    const int wc = lane & 3;        // 0..3

    for (int kt = 0; kt < NKT; kt++) {
        if (kt + 1 < NKT) {
            copy_tile((kt + 1) & 1, kt + 1);
            CP_COMMIT();
            CP_WAIT(1);
        } else {
            CP_WAIT(0);
        }
        __syncthreads();

        const uint32_t* base = (const uint32_t*)(smem + (kt & 1) * STAGE_B);
        const uint32_t* Ah = base;
        const uint32_t* Al = base + SPLANE_W;
        const uint32_t* Wh = base + 2 * SPLANE_W;
        const uint32_t* Wl = base + 3 * SPLANE_W;

#pragma unroll
        for (int ks = 0; ks < 2; ks++) {
            const int s8 = ks * 8 + wc;
            uint32_t ah[2][4], al[2][4];
#pragma unroll
            for (int mt = 0; mt < 2; mt++) {
                const int r = wm * 32 + mt * 16 + rq;
                ah[mt][0] = Ah[r * 20 + s8];
                ah[mt][1] = Ah[(r + 8) * 20 + s8];
                ah[mt][2] = Ah[r * 20 + s8 + 4];
                ah[mt][3] = Ah[(r + 8) * 20 + s8 + 4];
                al[mt][0] = Al[r * 20 + s8];
                al[mt][1] = Al[(r + 8) * 20 + s8];
                al[mt][2] = Al[r * 20 + s8 + 4];
                al[mt][3] = Al[(r + 8) * 20 + s8 + 4];
            }
#pragma unroll
            for (int nt = 0; nt < 8; nt++) {
                const int n = wn * 64 + nt * 8 + rq;
                uint32_t bh[2], bl[2];
                bh[0] = Wh[n * 20 + s8];
                bh[1] = Wh[n * 20 + s8 + 4];
                bl[0] = Wl[n * 20 + s8];
                bl[1] = Wl[n * 20 + s8 + 4];
                // bf16x3: hi*lo + lo*hi + hi*hi
                mma_bf16(acc[0][nt], ah[0], bl);
                mma_bf16(acc[1][nt], ah[1], bl);
                mma_bf16(acc[0][nt], al[0], bh);
                mma_bf16(acc[1][nt], al[1], bh);
                mma_bf16(acc[0][nt], ah[0], bh);
                mma_bf16(acc[1][nt], ah[1], bh);
            }
        }
        __syncthreads();
    }

    // Epilogue (C-fragment layout -> gmem)
#pragma unroll
    for (int mt = 0; mt < 2; mt++) {
        const int r = m0 + wm * 32 + mt * 16 + rq;
#pragma unroll
        for (int nt = 0; nt < 8; nt++) {
            const int c = n0 + wn * 64 + nt * 8 + (wc << 1);
            *(float2*)&C[(size_t)r * N + c]       = make_float2(acc[mt][nt][0], acc[mt][nt][1]);
            *(float2*)&C[(size_t)(r + 8) * N + c] = make_float2(acc[mt][nt][2], acc[mt][nt][3]);
        }
    }
}

// ---------------------------------------------------------------------------
// Flash attention (causal, GQA) — proven tf32 legacy-mma kernel.
// Epilogue emits bf16 hi/lo planes for the O-projection.
// ---------------------------------------------------------------------------
__device__ __forceinline__ uint32_t f2tf32(float v) {
    uint32_t r;
    asm("cvt.rna.tf32.f32 %0, %1;" : "=r"(r) : "f"(v));
    return r;
}
__device__ __forceinline__ void mma_tf32(float* d, const uint32_t* a, const uint32_t* b) {
    asm volatile(
        "mma.sync.aligned.m16n8k8.row.col.f32.tf32.tf32.f32 "
        "{%0,%1,%2,%3},{%4,%5,%6,%7},{%8,%9},{%0,%1,%2,%3};\n"
        : "+f"(d[0]), "+f"(d[1]), "+f"(d[2]), "+f"(d[3])
        : "r"(a[0]), "r"(a[1]), "r"(a[2]), "r"(a[3]), "r"(b[0]), "r"(b[1]));
}

#define QSTRIDE 68
#define VSTRIDE 72
#define ATTN_SMEM ((64 * QSTRIDE * 3 + 64 * VSTRIDE) * 4)

__global__ __launch_bounds__(128) void attn_kernel(
        const float* __restrict__ q, const float* __restrict__ kv,
        __nv_bfloat16* __restrict__ aohi, __nv_bfloat16* __restrict__ aolo) {
    extern __shared__ uint32_t sm[];
    uint32_t* Qs = sm;
    uint32_t* Ks = Qs + 64 * QSTRIDE;
    uint32_t* Ps = Ks + 64 * QSTRIDE;
    uint32_t* Vs = Ps + 64 * QSTRIDE;

    const int tid  = threadIdx.x;
    const int lane = tid & 31;
    const int w    = tid >> 5;
    const int qb   = blockIdx.x;
    const int bh   = blockIdx.y;
    const int b    = bh >> 5;
    const int hq   = bh & 31;
    const int hkv  = hq >> 2;

    const int ldrow = tid >> 4;
    const int ldcol = (tid & 15) << 2;

#pragma unroll
    for (int p = 0; p < 8; p++) {
        int row = p * 8 + ldrow;
        const float4 v = *(const float4*)&q[((size_t)(b * kT + qb * 64 + row)) * kE + hq * kHD + ldcol];
        *(uint4*)&Qs[row * QSTRIDE + ldcol] =
            make_uint4(f2tf32(v.x * 0.125f), f2tf32(v.y * 0.125f),
                       f2tf32(v.z * 0.125f), f2tf32(v.w * 0.125f));
    }

    float mrow0 = -INFINITY, mrow1 = -INFINITY;
    float lrow0 = 0.f, lrow1 = 0.f;
    float o[8][4];
#pragma unroll
    for (int nt = 0; nt < 8; nt++)
#pragma unroll
        for (int i = 0; i < 4; i++) o[nt][i] = 0.f;

    const int rloc = w * 16 + (lane >> 2);

    for (int j = 0; j <= qb; j++) {
#pragma unroll
        for (int p = 0; p < 8; p++) {
            int row = p * 8 + ldrow;
            size_t base = ((size_t)(b * kT + j * 64 + row)) * kKVN + hkv * kHD + ldcol;
            float4 kvr = *(const float4*)&kv[base];
            float4 vvr = *(const float4*)&kv[base + 512];
            *(uint4*)&Ks[row * QSTRIDE + ldcol] =
                make_uint4(f2tf32(kvr.x), f2tf32(kvr.y), f2tf32(kvr.z), f2tf32(kvr.w));
            *(uint4*)&Vs[row * VSTRIDE + ldcol] =
                make_uint4(f2tf32(vvr.x), f2tf32(vvr.y), f2tf32(vvr.z), f2tf32(vvr.w));
        }
        __syncthreads();

        float s[8][4];
#pragma unroll
        for (int nt = 0; nt < 8; nt++) { s[nt][0] = s[nt][1] = s[nt][2] = s[nt][3] = 0.f; }

#pragma unroll
        for (int k8 = 0; k8 < 8; k8++) {
            const int kk = k8 * 8 + (lane & 3);
            uint32_t a[4];
            a[0] = Qs[rloc * QSTRIDE + kk];
            a[1] = Qs[(rloc + 8) * QSTRIDE + kk];
            a[2] = Qs[rloc * QSTRIDE + kk + 4];
            a[3] = Qs[(rloc + 8) * QSTRIDE + kk + 4];
#pragma unroll
            for (int nt = 0; nt < 8; nt++) {
                const int kr = nt * 8 + (lane >> 2);
                uint32_t bb[2];
                bb[0] = Ks[kr * QSTRIDE + kk];
                bb[1] = Ks[kr * QSTRIDE + kk + 4];
                mma_tf32(s[nt], a, bb);
            }
        }

        if (j == qb) {
#pragma unroll
            for (int nt = 0; nt < 8; nt++) {
                int c0 = nt * 8 + ((lane & 3) << 1);
                if (c0     > rloc)     s[nt][0] = -INFINITY;
                if (c0 + 1 > rloc)     s[nt][1] = -INFINITY;
                if (c0     > rloc + 8) s[nt][2] = -INFINITY;
                if (c0 + 1 > rloc + 8) s[nt][3] = -INFINITY;
            }
        }

        float mx0 = -INFINITY, mx1 = -INFINITY;
#pragma unroll
        for (int nt = 0; nt < 8; nt++) {
            mx0 = fmaxf(mx0, fmaxf(s[nt][0], s[nt][1]));
            mx1 = fmaxf(mx1, fmaxf(s[nt][2], s[nt][3]));
        }
        mx0 = fmaxf(mx0, __shfl_xor_sync(0xffffffffu, mx0, 1));
        mx0 = fmaxf(mx0, __shfl_xor_sync(0xffffffffu, mx0, 2));
        mx1 = fmaxf(mx1, __shfl_xor_sync(0xffffffffu, mx1, 1));
        mx1 = fmaxf(mx1, __shfl_xor_sync(0xffffffffu, mx1, 2));

        float mnew0 = fmaxf(mrow0, mx0);
        float mnew1 = fmaxf(mrow1, mx1);
        float alpha0 = __expf(mrow0 - mnew0);
        float alpha1 = __expf(mrow1 - mnew1);
        mrow0 = mnew0; mrow1 = mnew1;

        float sum0 = 0.f, sum1 = 0.f;
#pragma unroll
        for (int nt = 0; nt < 8; nt++) {
            s[nt][0] = __expf(s[nt][0] - mnew0); sum0 += s[nt][0];
            s[nt][1] = __expf(s[nt][1] - mnew0); sum0 += s[nt][1];
            s[nt][2] = __expf(s[nt][2] - mnew1); sum1 += s[nt][2];
            s[nt][3] = __expf(s[nt][3] - mnew1); sum1 += s[nt][3];
        }
        sum0 += __shfl_xor_sync(0xffffffffu, sum0, 1);
        sum0 += __shfl_xor_sync(0xffffffffu, sum0, 2);
        sum1 += __shfl_xor_sync(0xffffffffu, sum1, 1);
        sum1 += __shfl_xor_sync(0xffffffffu, sum1, 2);

        lrow0 = lrow0 * alpha0 + sum0;
        lrow1 = lrow1 * alpha1 + sum1;

#pragma unroll
        for (int nt = 0; nt < 8; nt++) {
            o[nt][0] *= alpha0; o[nt][1] *= alpha0;
            o[nt][2] *= alpha1; o[nt][3] *= alpha1;
        }

#pragma unroll
        for (int nt = 0; nt < 8; nt++) {
            int pc = nt * 8 + ((lane & 3) << 1);
            Ps[rloc * QSTRIDE + pc]           = f2tf32(s[nt][0]);
            Ps[rloc * QSTRIDE + pc + 1]       = f2tf32(s[nt][1]);
            Ps[(rloc + 8) * QSTRIDE + pc]     = f2tf32(s[nt][2]);
            Ps[(rloc + 8) * QSTRIDE + pc + 1] = f2tf32(s[nt][3]);
        }
        __syncwarp();

#pragma unroll
        for (int k8 = 0; k8 < 8; k8++) {
            const int kk = k8 * 8 + (lane & 3);
            uint32_t a[4];
            a[0] = Ps[rloc * QSTRIDE + kk];
            a[1] = Ps[(rloc + 8) * QSTRIDE + kk];
            a[2] = Ps[rloc * QSTRIDE + kk + 4];
            a[3] = Ps[(rloc + 8) * QSTRIDE + kk + 4];
#pragma unroll
            for (int nt = 0; nt < 8; nt++) {
                uint32_t bb[2];
                bb[0] = Vs[kk * VSTRIDE + nt * 8 + (lane >> 2)];
                bb[1] = Vs[(kk + 4) * VSTRIDE + nt * 8 + (lane >> 2)];
                mma_tf32(o[nt], a, bb);
            }
        }
        __syncthreads();
    }

    // Normalize and emit bf16 hi/lo planes for the O-projection
    float inv0 = 1.f / lrow0;
    float inv1 = 1.f / lrow1;
    size_t r0 = (size_t)(b * kT + qb * 64 + rloc) * kE + hq * kHD;
    size_t r1 = (size_t)(b * kT + qb * 64 + rloc + 8) * kE + hq * kHD;
#pragma unroll
    for (int nt = 0; nt < 8; nt++) {
        int c = nt * 8 + ((lane & 3) << 1);
        float f00 = o[nt][0] * inv0, f01 = o[nt][1] * inv0;
        float f10 = o[nt][2] * inv1, f11 = o[nt][3] * inv1;
        __nv_bfloat16 h00, h01, h10, h11, l00, l01, l10, l11;
        splitbf(f00, h00, l00); splitbf(f01, h01, l01);
        splitbf(f10, h10, l10); splitbf(f11, h11, l11);
        *(__nv_bfloat162*)&aohi[r0 + c] = __nv_bfloat162(h00, h01);
        *(__nv_bfloat162*)&aolo[r0 + c] = __nv_bfloat162(l00, l01);
        *(__nv_bfloat162*)&aohi[r1 + c] = __nv_bfloat162(h10, h11);
        *(__nv_bfloat162*)&aolo[r1 + c] = __nv_bfloat162(l10, l11);
    }
}

// ---------------------------------------------------------------------------
// Launch
// ---------------------------------------------------------------------------
extern "C" void kernel_launch(void* const* d_in, const int* in_sizes, int n_in,
                              void* d_out, int out_size) {
    (void)in_sizes; (void)n_in; (void)out_size;
    const float* x   = (const float*)d_in[0];
    const float* Wq  = (const float*)d_in[1];
    const float* Wkv = (const float*)d_in[2];
    const float* Wo  = (const float*)d_in[3];
    float* out = (float*)d_out;

    float *q, *kvb;
    __nv_bfloat16 *xhi, *xlo, *wqhi, *wqlo, *wkvhi, *wkvlo, *wohi, *wolo, *aohi, *aolo;
    cudaGetSymbolAddress((void**)&q,     g_q);
    cudaGetSymbolAddress((void**)&kvb,   g_kv);
    cudaGetSymbolAddress((void**)&xhi,   g_xhi);
    cudaGetSymbolAddress((void**)&xlo,   g_xlo);
    cudaGetSymbolAddress((void**)&wqhi,  g_wqhi);
    cudaGetSymbolAddress((void**)&wqlo,  g_wqlo);
    cudaGetSymbolAddress((void**)&wkvhi, g_wkvhi);
    cudaGetSymbolAddress((void**)&wkvlo, g_wkvlo);
    cudaGetSymbolAddress((void**)&wohi,  g_wohi);
    cudaGetSymbolAddress((void**)&wolo,  g_wolo);
    cudaGetSymbolAddress((void**)&aohi,  g_aohi);
    cudaGetSymbolAddress((void**)&aolo,  g_aolo);

    cudaFuncSetAttribute(gemm_bf3,
                         cudaFuncAttributeMaxDynamicSharedMemorySize, GEMM_SMEM);
    cudaFuncSetAttribute(attn_kernel,
                         cudaFuncAttributeMaxDynamicSharedMemorySize, ATTN_SMEM);

    // Pre-split inputs to bf16 hi/lo planes
    const int nx   = kM * kE / 4,   nwq = kE * kE / 4;
    const int nwkv = kKVN * kE / 4, nwo = kE * kE / 4;
    split_kernel<<<(nx   + 255) / 256, 256>>>(x,   xhi,   xlo,   nx);
    split_kernel<<<(nwq  + 255) / 256, 256>>>(Wq,  wqhi,  wqlo,  nwq);
    split_kernel<<<(nwkv + 255) / 256, 256>>>(Wkv, wkvhi, wkvlo, nwkv);
    split_kernel<<<(nwo  + 255) / 256, 256>>>(Wo,  wohi,  wolo,  nwo);

    // Projections: bf16x3 on legacy tensor cores
    gemm_bf3<<<dim3(kE / 128,   kM / 128), 256, GEMM_SMEM>>>(xhi, xlo, wqhi,  wqlo,  q,   kE,   kE);
    gemm_bf3<<<dim3(kKVN / 128, kM / 128), 256, GEMM_SMEM>>>(xhi, xlo, wkvhi, wkvlo, kvb, kKVN, kE);

    // Attention (tf32 legacy mma), emits bf16 hi/lo
    attn_kernel<<<dim3(kT / 64, kB * kHQ), 128, ATTN_SMEM>>>(q, kvb, aohi, aolo);

    // O-projection
    gemm_bf3<<<dim3(kE / 128,   kM / 128), 256, GEMM_SMEM>>>(aohi, aolo, wohi, wolo, out, kE, kE);
}